// round 2
// baseline (speedup 1.0000x reference)
#include <cuda_runtime.h>
#include <math.h>

#define BB 4
#define TT 2048
#define DD 1024
#define KQ 32
#define NT (BB*TT)      // 8192 rows
#define KTOP 4

// Scratch (no allocations allowed)
__device__ float g_Q[NT*KQ];
__device__ float g_K[NT*KQ];
__device__ __align__(16) int g_idx[NT*KTOP];

// ---- packed f32x2 helpers (sm_103a FFMA2 path) ------------------------------
__device__ __forceinline__ unsigned long long pack2(float lo, float hi) {
    unsigned long long r;
    asm("mov.b64 %0, {%1, %2};" : "=l"(r) : "f"(lo), "f"(hi));
    return r;
}
__device__ __forceinline__ void unpack2(unsigned long long v, float& lo, float& hi) {
    asm("mov.b64 {%0, %1}, %2;" : "=f"(lo), "=f"(hi) : "l"(v));
}
__device__ __forceinline__ unsigned long long ffma2(unsigned long long a,
                                                    unsigned long long b,
                                                    unsigned long long c) {
    unsigned long long d;
    asm("fma.rn.f32x2 %0, %1, %2, %3;" : "=l"(d) : "l"(a), "l"(b), "l"(c));
    return d;
}

// ---------------------------------------------------------------------------
// Kernel 1: fused Q/K projection. [8192,1024] x [1024,64]
// 32 rows/block (grid=256), 256 threads, 2 rows x 4 cols per thread via FFMA2.
// ---------------------------------------------------------------------------
__global__ __launch_bounds__(256) void proj_kernel(
    const float* __restrict__ x, const float* __restrict__ Wq,
    const float* __restrict__ bq, const float* __restrict__ Wk,
    const float* __restrict__ bk)
{
    __shared__ float Xs[32][68];
    __shared__ float Ws[64][64];   // Ws[kk][col]

    const int tid  = threadIdx.x;
    const int row0 = blockIdx.x * 32;
    const int tr   = tid >> 4;     // 0..15 -> row pair
    const int tc   = tid & 15;     // 0..15 -> col group of 4

    unsigned long long acc00 = 0ULL, acc01 = 0ULL, acc10 = 0ULL, acc11 = 0ULL;

    for (int k0 = 0; k0 < DD; k0 += 64) {
        // X tile: 32x64 = 512 float4, 2 per thread
        #pragma unroll
        for (int l = 0; l < 2; l++) {
            int f  = tid + l * 256;
            int r  = f >> 4;
            int c4 = f & 15;
            *(float4*)&Xs[r][c4 * 4] =
                *(const float4*)&x[(size_t)(row0 + r) * DD + k0 + c4 * 4];
        }
        // W tile transposed: Ws[kk][col] = W[col][k0+kk]
        {
            int col = tid & 63;
            int kg  = tid >> 6;    // 0..3
            const float* Wrow = (col < KQ) ? &Wq[col * DD] : &Wk[(col - KQ) * DD];
            #pragma unroll
            for (int l = 0; l < 4; l++) {
                int kk = kg * 16 + l * 4;
                float4 w = *(const float4*)&Wrow[k0 + kk];
                Ws[kk + 0][col] = w.x;
                Ws[kk + 1][col] = w.y;
                Ws[kk + 2][col] = w.z;
                Ws[kk + 3][col] = w.w;
            }
        }
        __syncthreads();

        #pragma unroll
        for (int k4 = 0; k4 < 16; k4++) {
            float4 xa = *(const float4*)&Xs[tr * 2 + 0][k4 * 4];
            float4 xb = *(const float4*)&Xs[tr * 2 + 1][k4 * 4];
            const float* xav = (const float*)&xa;
            const float* xbv = (const float*)&xb;
            #pragma unroll
            for (int kk = 0; kk < 4; kk++) {
                ulonglong2 wv = *(const ulonglong2*)&Ws[k4 * 4 + kk][tc * 4];
                unsigned long long xap = pack2(xav[kk], xav[kk]);
                unsigned long long xbp = pack2(xbv[kk], xbv[kk]);
                acc00 = ffma2(xap, wv.x, acc00);
                acc01 = ffma2(xap, wv.y, acc01);
                acc10 = ffma2(xbp, wv.x, acc10);
                acc11 = ffma2(xbp, wv.y, acc11);
            }
        }
        __syncthreads();
    }

    // Epilogue: bias + write. Column group of 4 is entirely in Q or K half.
    float c0, c1, c2, c3;
    const int cbase = tc * 4;
    #pragma unroll
    for (int i = 0; i < 2; i++) {
        int r = row0 + tr * 2 + i;
        if (i == 0) { unpack2(acc00, c0, c1); unpack2(acc01, c2, c3); }
        else        { unpack2(acc10, c0, c1); unpack2(acc11, c2, c3); }
        if (cbase < KQ) {
            float4 o = { c0 + bq[cbase + 0], c1 + bq[cbase + 1],
                         c2 + bq[cbase + 2], c3 + bq[cbase + 3] };
            *(float4*)&g_Q[r * KQ + cbase] = o;
        } else {
            int cb = cbase - KQ;
            float4 o = { c0 + bk[cb + 0], c1 + bk[cb + 1],
                         c2 + bk[cb + 2], c3 + bk[cb + 3] };
            *(float4*)&g_K[r * KQ + cb] = o;
        }
    }
}

// ---------------------------------------------------------------------------
// Kernel 2: similarity + streaming top-4.
// 32 rows/block (grid=256), 256 threads, 8 s-partitions per row, FFMA2 dots.
// ---------------------------------------------------------------------------
__global__ __launch_bounds__(256) void sim_topk_kernel()
{
    __shared__ float Ks[128][36];   // 128 keys x 32 dims (+4 pad, 16B-aligned rows)
    __shared__ float Mv[1024];
    __shared__ int   Mi[1024];

    const int tid  = threadIdx.x;
    const int row0 = blockIdx.x * 32;
    const int b    = row0 >> 11;
    const int rl   = tid >> 3;      // 0..31 local row
    const int sub  = tid & 7;       // s partition
    const int trow = row0 + rl;

    // q: 16 packed f32x2 pairs
    unsigned long long q[16];
    {
        const ulonglong2* qp = (const ulonglong2*)&g_Q[trow * KQ];
        #pragma unroll
        for (int i = 0; i < 8; i++) {
            ulonglong2 v = qp[i];
            q[2 * i] = v.x; q[2 * i + 1] = v.y;
        }
    }

    float v0 = -INFINITY, v1 = -INFINITY, v2 = -INFINITY, v3 = -INFINITY;
    int   i0 = 0, i1 = 0, i2 = 0, i3 = 0;

    const float* Kb = &g_K[b * TT * KQ];

    for (int s0 = 0; s0 < TT; s0 += 128) {
        // stage K tile: 128 x 32 = 1024 float4
        #pragma unroll
        for (int l = 0; l < 4; l++) {
            int f = tid + l * 256;
            int r = f >> 3;
            int c = f & 7;
            *(float4*)&Ks[r][c * 4] =
                *(const float4*)&Kb[(s0 + r) * KQ + c * 4];
        }
        __syncthreads();

        #pragma unroll 4
        for (int j = 0; j < 16; j++) {
            int sl = sub + 8 * j;
            const ulonglong2* kp = (const ulonglong2*)&Ks[sl][0];
            unsigned long long a0 = 0ULL, a1 = 0ULL;
            #pragma unroll
            for (int i = 0; i < 8; i++) {
                ulonglong2 kv = kp[i];
                a0 = ffma2(q[2 * i],     kv.x, a0);
                a1 = ffma2(q[2 * i + 1], kv.y, a1);
            }
            float l0, h0, l1, h1;
            unpack2(a0, l0, h0);
            unpack2(a1, l1, h1);
            float v = (l0 + h0) + (l1 + h1);
            int  si = s0 + sl;
            if (v > v3) {
                if (v > v1) {
                    v3 = v2; i3 = i2; v2 = v1; i2 = i1;
                    if (v > v0) { v1 = v0; i1 = i0; v0 = v; i0 = si; }
                    else        { v1 = v;  i1 = si; }
                } else {
                    if (v > v2) { v3 = v2; i3 = i2; v2 = v; i2 = si; }
                    else        { v3 = v;  i3 = si; }
                }
            }
        }
        __syncthreads();
    }

    // merge 8 partial top-4 lists per row
    Mv[tid * 4 + 0] = v0; Mi[tid * 4 + 0] = i0;
    Mv[tid * 4 + 1] = v1; Mi[tid * 4 + 1] = i1;
    Mv[tid * 4 + 2] = v2; Mi[tid * 4 + 2] = i2;
    Mv[tid * 4 + 3] = v3; Mi[tid * 4 + 3] = i3;
    __syncthreads();

    if (sub == 0) {
        // tid = rl*8 -> tid*4 = rl*32: contiguous 32 candidates for this row
        float cv[32]; int ci[32];
        #pragma unroll
        for (int k = 0; k < 32; k++) {
            cv[k] = Mv[tid * 4 + k];
            ci[k] = Mi[tid * 4 + k];
        }
        int outbase = trow * KTOP;
        #pragma unroll
        for (int p = 0; p < KTOP; p++) {
            int best = 0;
            #pragma unroll
            for (int k = 1; k < 32; k++)
                if (cv[k] > cv[best]) best = k;
            g_idx[outbase + p] = ci[best];
            cv[best] = -INFINITY;
        }
    }
}

// ---------------------------------------------------------------------------
// Kernel 3: gather 4 neighbor rows + mean. One block per (b,t) row.
// ---------------------------------------------------------------------------
__global__ __launch_bounds__(256) void gather_kernel(
    const float* __restrict__ x, float* __restrict__ out)
{
    const int row = blockIdx.x;
    const int b   = row >> 11;
    const int4 iv = *(const int4*)&g_idx[row * 4];

    const float4* xb = (const float4*)(x + (size_t)b * TT * DD);
    const float4* r0 = xb + (size_t)iv.x * (DD / 4);
    const float4* r1 = xb + (size_t)iv.y * (DD / 4);
    const float4* r2 = xb + (size_t)iv.z * (DD / 4);
    const float4* r3 = xb + (size_t)iv.w * (DD / 4);

    const int c = threadIdx.x;
    float4 a = r0[c], bq4 = r1[c], cq = r2[c], dq = r3[c];
    float4 o;
    o.x = (a.x + bq4.x + cq.x + dq.x) * 0.25f;
    o.y = (a.y + bq4.y + cq.y + dq.y) * 0.25f;
    o.z = (a.z + bq4.z + cq.z + dq.z) * 0.25f;
    o.w = (a.w + bq4.w + cq.w + dq.w) * 0.25f;
    ((float4*)out)[(size_t)row * (DD / 4) + c] = o;
}

// ---------------------------------------------------------------------------
extern "C" void kernel_launch(void* const* d_in, const int* in_sizes, int n_in,
                              void* d_out, int out_size)
{
    const float* x  = (const float*)d_in[0];
    const float* Wq = (const float*)d_in[1];
    const float* bq = (const float*)d_in[2];
    const float* Wk = (const float*)d_in[3];
    const float* bk = (const float*)d_in[4];
    float* out = (float*)d_out;

    proj_kernel<<<NT / 32, 256>>>(x, Wq, bq, Wk, bk);
    sim_topk_kernel<<<NT / 32, 256>>>();
    gather_kernel<<<NT, 256>>>(x, out);
}

// round 3
// speedup vs baseline: 1.3013x; 1.3013x over previous
#include <cuda_runtime.h>
#include <math.h>

#define TT 2048
#define DD 1024
#define KQ 32
#define NT 8192        // 4*2048 rows
#define KTOP 4

typedef unsigned long long ull;

// Partial projections: g_P[kh][row*64 + c], cols 0..31 = Q, 32..63 = K.
__device__ float g_P[2][NT * 64];

// ---- packed f32x2 helpers ---------------------------------------------------
__device__ __forceinline__ void unpack2(ull v, float& lo, float& hi) {
    asm("mov.b64 {%0, %1}, %2;" : "=f"(lo), "=f"(hi) : "l"(v));
}
__device__ __forceinline__ ull ffma2(ull a, ull b, ull c) {
    ull d;
    asm("fma.rn.f32x2 %0, %1, %2, %3;" : "=l"(d) : "l"(a), "l"(b), "l"(c));
    return d;
}

// ---------------------------------------------------------------------------
// Kernel 1: Q/K projection, k-split x2.  grid = 256 blocks x 128 threads.
// Block: 64 rows x 64 cols x 512 k.  Thread: 4 rows x 4 col-pairs (FFMA2).
// X staged DUPLICATED (x,x) pairs -> FFMA2 'a' operand needs no packing.
// ---------------------------------------------------------------------------
__global__ __launch_bounds__(128) void proj_kernel(
    const float* __restrict__ x, const float* __restrict__ Wq,
    const float* __restrict__ bq, const float* __restrict__ Wk,
    const float* __restrict__ bk)
{
    __shared__ __align__(16) float Xd[32][132];  // [k][2*row] duplicated pairs
    __shared__ __align__(16) float Wt[32][68];   // [k][col]

    const int tid  = threadIdx.x;
    const int bid  = blockIdx.x;
    const int row0 = (bid >> 1) * 64;
    const int kh   = bid & 1;
    const int rg   = tid >> 3;      // 0..15
    const int cg   = tid & 7;       // 0..7
    const int r0   = rg * 4;

    ull acc[4][4];
    #pragma unroll
    for (int i = 0; i < 4; i++)
        #pragma unroll
        for (int j = 0; j < 4; j++) acc[i][j] = 0ULL;

    for (int kt = 0; kt < 16; kt++) {
        const int kb = kh * 512 + kt * 32;
        // stage X (64 rows x 32 k), duplicated pairs
        #pragma unroll
        for (int l = 0; l < 4; l++) {
            int f = tid + l * 128;
            int row = f >> 3, kc = f & 7;
            float4 v = *(const float4*)&x[(size_t)(row0 + row) * DD + kb + kc * 4];
            *(float2*)&Xd[kc * 4 + 0][2 * row] = make_float2(v.x, v.x);
            *(float2*)&Xd[kc * 4 + 1][2 * row] = make_float2(v.y, v.y);
            *(float2*)&Xd[kc * 4 + 2][2 * row] = make_float2(v.z, v.z);
            *(float2*)&Xd[kc * 4 + 3][2 * row] = make_float2(v.w, v.w);
        }
        // stage W transposed (64 cols x 32 k)
        #pragma unroll
        for (int l = 0; l < 4; l++) {
            int f = tid + l * 128;
            int col = f >> 3, kc = f & 7;
            const float* Wr = (col < KQ) ? &Wq[col * DD] : &Wk[(col - KQ) * DD];
            float4 w = *(const float4*)&Wr[kb + kc * 4];
            Wt[kc * 4 + 0][col] = w.x;
            Wt[kc * 4 + 1][col] = w.y;
            Wt[kc * 4 + 2][col] = w.z;
            Wt[kc * 4 + 3][col] = w.w;
        }
        __syncthreads();

        #pragma unroll
        for (int k = 0; k < 32; k++) {
            ulonglong2 xa = *(const ulonglong2*)&Xd[k][2 * r0];      // rows r0,r0+1
            ulonglong2 xb = *(const ulonglong2*)&Xd[k][2 * r0 + 4];  // rows r0+2,r0+3
            ull w0 = *(const ull*)&Wt[k][2 * cg];        // col pair cg
            ull w1 = *(const ull*)&Wt[k][2 * cg + 16];   // col pair cg+8
            ull w2 = *(const ull*)&Wt[k][2 * cg + 32];   // col pair cg+16
            ull w3 = *(const ull*)&Wt[k][2 * cg + 48];   // col pair cg+24
            ull xr[4] = { xa.x, xa.y, xb.x, xb.y };
            #pragma unroll
            for (int i = 0; i < 4; i++) {
                acc[i][0] = ffma2(xr[i], w0, acc[i][0]);
                acc[i][1] = ffma2(xr[i], w1, acc[i][1]);
                acc[i][2] = ffma2(xr[i], w2, acc[i][2]);
                acc[i][3] = ffma2(xr[i], w3, acc[i][3]);
            }
        }
        __syncthreads();
    }

    // epilogue: bias (only kh==0) + store partials
    #pragma unroll
    for (int i = 0; i < 4; i++) {
        int r = row0 + r0 + i;
        #pragma unroll
        for (int j = 0; j < 4; j++) {
            int c = 2 * (cg + 8 * j);
            float lo, hi;
            unpack2(acc[i][j], lo, hi);
            if (kh == 0) {
                if (c < KQ) { lo += bq[c];      hi += bq[c + 1]; }
                else        { lo += bk[c - KQ]; hi += bk[c - KQ + 1]; }
            }
            *(float2*)&g_P[kh][(size_t)r * 64 + c] = make_float2(lo, hi);
        }
    }
}

// ---------------------------------------------------------------------------
// Kernel 2: similarity GEMM + streaming top-4 + fused gather/mean.
// grid = 256 blocks x 128 threads. Block: 32 rows x all 2048 keys (16 tiles of 128).
// Thread: 4 rows x 4 key-pairs per tile (FFMA2), conflict-free strided pairs.
// ---------------------------------------------------------------------------
__device__ __forceinline__ void upd4(float* v, int* ix, float s, int si) {
    if (s > v[3]) {
        if (s > v[1]) {
            v[3] = v[2]; ix[3] = ix[2]; v[2] = v[1]; ix[2] = ix[1];
            if (s > v[0]) { v[1] = v[0]; ix[1] = ix[0]; v[0] = s; ix[0] = si; }
            else          { v[1] = s; ix[1] = si; }
        } else {
            if (s > v[2]) { v[3] = v[2]; ix[3] = ix[2]; v[2] = s; ix[2] = si; }
            else          { v[3] = s; ix[3] = si; }
        }
    }
}

__global__ __launch_bounds__(128) void sim_gather_kernel(
    const float* __restrict__ x, float* __restrict__ out)
{
    __shared__ __align__(16) float Qd[32][68];    // [k][2*row] duplicated pairs
    __shared__ __align__(16) float Kt[32][132];   // [k][key]
    __shared__ float Mv[32][64];
    __shared__ int   Mi[32][64];
    __shared__ __align__(16) int sel[32][4];

    const int tid  = threadIdx.x;
    const int row0 = blockIdx.x * 32;
    const int b    = row0 >> 11;
    const int rg   = tid >> 4;      // 0..7
    const int cg   = tid & 15;      // 0..15
    const int r0   = rg * 4;

    // stage Q (32 rows x 32 k), sum partials, duplicate pairs
    #pragma unroll
    for (int l = 0; l < 2; l++) {
        int f = tid + l * 128;
        int row = f >> 3, kc = f & 7;
        size_t base = (size_t)(row0 + row) * 64 + kc * 4;
        float4 a = *(const float4*)&g_P[0][base];
        float4 c4 = *(const float4*)&g_P[1][base];
        float s0 = a.x + c4.x, s1 = a.y + c4.y, s2 = a.z + c4.z, s3 = a.w + c4.w;
        *(float2*)&Qd[kc * 4 + 0][2 * row] = make_float2(s0, s0);
        *(float2*)&Qd[kc * 4 + 1][2 * row] = make_float2(s1, s1);
        *(float2*)&Qd[kc * 4 + 2][2 * row] = make_float2(s2, s2);
        *(float2*)&Qd[kc * 4 + 3][2 * row] = make_float2(s3, s3);
    }

    float tv[4][4]; int ti[4][4];
    #pragma unroll
    for (int i = 0; i < 4; i++)
        #pragma unroll
        for (int p = 0; p < 4; p++) { tv[i][p] = -INFINITY; ti[i][p] = 0; }

    __syncthreads();

    for (int t = 0; t < 16; t++) {
        const int kbase = t * 128;
        // stage K tile (128 keys x 32 k), sum partials
        #pragma unroll
        for (int l = 0; l < 8; l++) {
            int f = tid + l * 128;
            int key = f >> 3, kc = f & 7;
            size_t base = (size_t)(b * TT + kbase + key) * 64 + KQ + kc * 4;
            float4 a = *(const float4*)&g_P[0][base];
            float4 c4 = *(const float4*)&g_P[1][base];
            Kt[kc * 4 + 0][key] = a.x + c4.x;
            Kt[kc * 4 + 1][key] = a.y + c4.y;
            Kt[kc * 4 + 2][key] = a.z + c4.z;
            Kt[kc * 4 + 3][key] = a.w + c4.w;
        }
        __syncthreads();

        ull acc[4][4];
        #pragma unroll
        for (int i = 0; i < 4; i++)
            #pragma unroll
            for (int j = 0; j < 4; j++) acc[i][j] = 0ULL;

        #pragma unroll
        for (int k = 0; k < 32; k++) {
            ulonglong2 qa = *(const ulonglong2*)&Qd[k][2 * r0];
            ulonglong2 qb = *(const ulonglong2*)&Qd[k][2 * r0 + 4];
            ull k0 = *(const ull*)&Kt[k][2 * cg];        // key pair cg
            ull k1 = *(const ull*)&Kt[k][2 * cg + 32];   // key pair cg+16
            ull k2 = *(const ull*)&Kt[k][2 * cg + 64];   // key pair cg+32
            ull k3 = *(const ull*)&Kt[k][2 * cg + 96];   // key pair cg+48
            ull qr[4] = { qa.x, qa.y, qb.x, qb.y };
            #pragma unroll
            for (int i = 0; i < 4; i++) {
                acc[i][0] = ffma2(qr[i], k0, acc[i][0]);
                acc[i][1] = ffma2(qr[i], k1, acc[i][1]);
                acc[i][2] = ffma2(qr[i], k2, acc[i][2]);
                acc[i][3] = ffma2(qr[i], k3, acc[i][3]);
            }
        }

        // top-4 update (scale 1/sqrt(32) omitted: monotonic)
        #pragma unroll
        for (int i = 0; i < 4; i++) {
            #pragma unroll
            for (int j = 0; j < 4; j++) {
                float lo, hi;
                unpack2(acc[i][j], lo, hi);
                int idx = kbase + 2 * (cg + 16 * j);
                upd4(tv[i], ti[i], lo, idx);
                upd4(tv[i], ti[i], hi, idx + 1);
            }
        }
        __syncthreads();   // Kt reused next tile
    }

    // merge candidates: 16 col-threads x 4 per row
    #pragma unroll
    for (int i = 0; i < 4; i++) {
        int rl = r0 + i;
        #pragma unroll
        for (int p = 0; p < 4; p++) {
            Mv[rl][cg * 4 + p] = tv[i][p];
            Mi[rl][cg * 4 + p] = ti[i][p];
        }
    }
    __syncthreads();

    if (tid < 32) {
        int rl = tid;
        #pragma unroll
        for (int p = 0; p < KTOP; p++) {
            float best = -INFINITY; int bk2 = 0;
            for (int k = 0; k < 64; k++) {
                float v = Mv[rl][k];
                if (v > best) { best = v; bk2 = k; }
            }
            sel[rl][p] = Mi[rl][bk2];
            Mv[rl][bk2] = -INFINITY;
        }
    }
    __syncthreads();

    // fused gather + mean
    const float4* xb4 = (const float4*)(x + (size_t)b * TT * DD);
    float4* out4 = (float4*)out;
    for (int rl = 0; rl < 32; rl++) {
        int4 iv = *(const int4*)&sel[rl][0];
        #pragma unroll
        for (int h = 0; h < 2; h++) {
            int c = tid + h * 128;
            float4 A = xb4[(size_t)iv.x * 256 + c];
            float4 B = xb4[(size_t)iv.y * 256 + c];
            float4 C = xb4[(size_t)iv.z * 256 + c];
            float4 D = xb4[(size_t)iv.w * 256 + c];
            float4 o;
            o.x = (A.x + B.x + C.x + D.x) * 0.25f;
            o.y = (A.y + B.y + C.y + D.y) * 0.25f;
            o.z = (A.z + B.z + C.z + D.z) * 0.25f;
            o.w = (A.w + B.w + C.w + D.w) * 0.25f;
            out4[(size_t)(row0 + rl) * 256 + c] = o;
        }
    }
}

// ---------------------------------------------------------------------------
extern "C" void kernel_launch(void* const* d_in, const int* in_sizes, int n_in,
                              void* d_out, int out_size)
{
    const float* x  = (const float*)d_in[0];
    const float* Wq = (const float*)d_in[1];
    const float* bq = (const float*)d_in[2];
    const float* Wk = (const float*)d_in[3];
    const float* bk = (const float*)d_in[4];
    float* out = (float*)d_out;

    proj_kernel<<<256, 128>>>(x, Wq, bq, Wk, bk);
    sim_gather_kernel<<<256, 128>>>(x, out);
}